// round 3
// baseline (speedup 1.0000x reference)
#include <cuda_runtime.h>
#include <math.h>

// Problem constants
#define NB   64
#define LSEQ 510
#define DDIM 768
#define L1   128
#define KN   20
#define OUTD 300
#define NPAD 320
#define EPSV 1e-5f

// GEMM tiling
#define TM 32
#define KC 16
#define NCHUNK (DDIM / KC)   // 48
#define NBLK1 (NB * L1 / TM) // 256
#define NBLKK (NB * KN / TM) // 40
#define NBLK  (NBLK1 + NBLKK)

// Output layout (concatenated, reference tuple order)
#define H1_OFF    0
#define SCORE_OFF (NB * L1 * OUTD)                 // 2457600
#define HK_OFF    (2 * NB * L1 * OUTD)             // 4915200
#define SK_OFF    (HK_OFF + NB * KN * OUTD)        // 5299200

// Scratch
__device__ __align__(16) float g_WT[DDIM * NPAD];  // W_lin transposed+padded: [k][n]
__device__ float g_scores[NB * L1 + NB * KN];      // raw scores before softmax
__device__ int   g_mask_mode;                      // 0=uint8, 1=int32, 2=float32

// ---------------------------------------------------------------------------
// Mask dtype detection: bool masks may arrive as uint8 (1B), int32, or float32.
// uint8: bytes are 0/1, nonzero at indices !≡0 (mod 4) (contiguous suffix of 1s).
// int32: little-endian 0/1 -> nonzero bytes only at i%4==0.
// float32 1.0f: bytes 0x80/0x3f appear -> "weird" bytes (>1).
// Reading the first (n_elems) bytes is safe under every interpretation.
// ---------------------------------------------------------------------------
__global__ void detect_mask_kernel(const unsigned char* __restrict__ mk,
                                   const unsigned char* __restrict__ m1) {
    __shared__ int f_weird, f_odd;
    int t = threadIdx.x;
    if (t == 0) { f_weird = 0; f_odd = 0; }
    __syncthreads();
    int lw = 0, lo = 0;
    for (int i = t; i < NB * KN; i += 256) {
        unsigned char v = mk[i];
        if (v > 1) lw = 1;
        if (v && (i & 3)) lo = 1;
    }
    for (int i = t; i < NB * L1; i += 256) {
        unsigned char v = m1[i];
        if (v > 1) lw = 1;
        if (v && (i & 3)) lo = 1;
    }
    if (lw) atomicOr(&f_weird, 1);
    if (lo) atomicOr(&f_odd, 1);
    __syncthreads();
    if (t == 0) g_mask_mode = f_weird ? 2 : (f_odd ? 0 : 1);
}

__device__ __forceinline__ bool read_mask(const void* m, int i, int mode) {
    if (mode == 0) return ((const unsigned char*)m)[i] != 0;
    if (mode == 1) return ((const int*)m)[i] != 0;
    return ((const float*)m)[i] != 0.0f;
}

// ---------------------------------------------------------------------------
// Transpose W_lin (OUTD x DDIM) -> g_WT (DDIM x NPAD), zero pad n>=OUTD.
// ---------------------------------------------------------------------------
__global__ void transpose_w_kernel(const float* __restrict__ W) {
    __shared__ float tile[32][33];
    int k0 = blockIdx.x * 32;   // 24 tiles over DDIM
    int n0 = blockIdx.y * 32;   // 10 tiles over NPAD
    int tx = threadIdx.x, ty = threadIdx.y; // 32 x 8
    #pragma unroll
    for (int r = ty; r < 32; r += 8) {
        int n = n0 + r;
        tile[r][tx] = (n < OUTD) ? W[n * DDIM + k0 + tx] : 0.0f;
    }
    __syncthreads();
    #pragma unroll
    for (int r = ty; r < 32; r += 8) {
        g_WT[(k0 + r) * NPAD + n0 + tx] = tile[tx][r];
    }
}

// ---------------------------------------------------------------------------
// Fused: span-mean pooling + GEMM (pooled @ W_lin^T + b) + LayerNorm + score.
// Block = TM spans x NPAD outputs. 256 threads: ty=warp (8) x tx=lane (32).
// Thread computes 4 spans (m = ty*4+mm) x 10 outputs (pairs p = tx+32i).
// Packed f32x2 FMAs double fp32 throughput.
// ---------------------------------------------------------------------------
__global__ __launch_bounds__(256, 2)
void gemm_ln_kernel(const float* __restrict__ t1, const float* __restrict__ know,
                    const int* __restrict__ s1s, const int* __restrict__ s1e,
                    const int* __restrict__ sks, const int* __restrict__ ske,
                    const float* __restrict__ b_lin, const float* __restrict__ gamma,
                    const float* __restrict__ beta, const float* __restrict__ w_score,
                    const float* __restrict__ b_score, float* __restrict__ out) {
    __shared__ float As[TM][KC + 1];
    __shared__ __align__(16) float Bs[KC][NPAD];
    __shared__ float sb[NPAD], sg[NPAD], sbe[NPAD], sw[NPAD];
    __shared__ int   sm_start[TM];
    __shared__ int   sm_len[TM];
    __shared__ float sm_inv[TM];

    const int t   = threadIdx.x;
    const int blk = blockIdx.x;
    const bool isK = (blk >= NBLK1);
    const float* __restrict__ src = isK ? know : t1;
    const int tilebase = (isK ? (blk - NBLK1) : blk) * TM;
    const int per = isK ? KN : L1;

    for (int i = t; i < NPAD; i += 256) {
        sb[i]  = (i < OUTD) ? b_lin[i]   : 0.0f;
        sg[i]  = (i < OUTD) ? gamma[i]   : 0.0f;
        sbe[i] = (i < OUTD) ? beta[i]    : 0.0f;
        sw[i]  = (i < OUTD) ? w_score[i] : 0.0f;
    }
    if (t < TM) {
        int g = tilebase + t;
        int b = g / per, idx = g % per;
        int s = (isK ? sks : s1s)[b * per + idx];
        int e = (isK ? ske : s1e)[b * per + idx];
        int len = e - s; if (len < 1) len = 1;
        sm_start[t] = (b * LSEQ + s) * DDIM;
        sm_len[t]   = len;
        sm_inv[t]   = 1.0f / (float)len;
    }
    __syncthreads();

    unsigned long long acc[4][5];
    #pragma unroll
    for (int mm = 0; mm < 4; mm++)
        #pragma unroll
        for (int i = 0; i < 5; i++) acc[mm][i] = 0ULL;

    const int ty = t >> 5, tx = t & 31;

    for (int kc = 0; kc < DDIM; kc += KC) {
        // ---- A tile: pooled[m][kk] = mean over span rows (len <= 4) ----
        #pragma unroll
        for (int j = 0; j < 2; j++) {
            int e2 = t + 256 * j;            // 0..511 over 32x16
            int m  = e2 >> 4, kk = e2 & 15;
            int base = sm_start[m] + kc + kk;
            int len  = sm_len[m];
            float s = 0.0f;
            for (int r = 0; r < len; r++) s += src[base + r * DDIM];
            As[m][kk] = s * sm_inv[m];
        }
        // ---- B tile: g_WT[kc..kc+KC)[0..NPAD) via float4 ----
        {
            const float4* wt4 = (const float4*)(g_WT + kc * NPAD);
            float4* bs4 = (float4*)&Bs[0][0];
            #pragma unroll
            for (int j = 0; j < 5; j++) {
                int e4 = t + 256 * j;        // 1280 float4
                bs4[e4] = wt4[e4];
            }
        }
        __syncthreads();
        // ---- compute ----
        #pragma unroll
        for (int kk = 0; kk < KC; kk++) {
            unsigned long long a2[4];
            #pragma unroll
            for (int mm = 0; mm < 4; mm++) {
                unsigned int ab = __float_as_uint(As[ty * 4 + mm][kk]);
                asm("mov.b64 %0, {%1, %1};" : "=l"(a2[mm]) : "r"(ab));
            }
            #pragma unroll
            for (int i = 0; i < 5; i++) {
                int p = tx + 32 * i;
                unsigned long long bp =
                    *(const unsigned long long*)&Bs[kk][2 * p];
                #pragma unroll
                for (int mm = 0; mm < 4; mm++)
                    asm("fma.rn.f32x2 %0, %1, %2, %0;"
                        : "+l"(acc[mm][i]) : "l"(a2[mm]), "l"(bp));
            }
        }
        __syncthreads();
    }

    // ---- epilogue: bias + LayerNorm + write h + score dot ----
    const float inv_out = 1.0f / (float)OUTD;
    const int region_base = isK ? HK_OFF : H1_OFF;
    const float bsc = b_score[0];
    #pragma unroll
    for (int mm = 0; mm < 4; mm++) {
        const int m = ty * 4 + mm;
        const int g = tilebase + m;
        float lo[5], hi[5];
        float ssum = 0.0f;
        #pragma unroll
        for (int i = 0; i < 5; i++) {
            unsigned int u0, u1;
            asm("mov.b64 {%0, %1}, %2;" : "=r"(u0), "=r"(u1) : "l"(acc[mm][i]));
            int n0 = 2 * (tx + 32 * i);
            lo[i] = __uint_as_float(u0) + sb[n0];
            hi[i] = __uint_as_float(u1) + sb[n0 + 1];
            ssum += lo[i] + hi[i];    // pad lanes contribute exact 0
        }
        #pragma unroll
        for (int o = 16; o; o >>= 1) ssum += __shfl_xor_sync(0xffffffffu, ssum, o);
        float mean = ssum * inv_out;
        float vs = 0.0f;
        #pragma unroll
        for (int i = 0; i < 5; i++) {
            if (i < 4 || tx < 22) {   // pairs p<150 are real (n<300)
                float d0 = lo[i] - mean, d1 = hi[i] - mean;
                vs += d0 * d0 + d1 * d1;
            }
        }
        #pragma unroll
        for (int o = 16; o; o >>= 1) vs += __shfl_xor_sync(0xffffffffu, vs, o);
        float rstd = rsqrtf(vs * inv_out + EPSV);
        float sc = 0.0f;
        float* orow = out + region_base + (long)g * OUTD;
        #pragma unroll
        for (int i = 0; i < 5; i++) {
            if (i < 4 || tx < 22) {
                int n0 = 2 * (tx + 32 * i);
                float h0 = (lo[i] - mean) * rstd * sg[n0]     + sbe[n0];
                float h1 = (hi[i] - mean) * rstd * sg[n0 + 1] + sbe[n0 + 1];
                *(float2*)(orow + n0) = make_float2(h0, h1);
                sc += h0 * sw[n0] + h1 * sw[n0 + 1];
            }
        }
        #pragma unroll
        for (int o = 16; o; o >>= 1) sc += __shfl_xor_sync(0xffffffffu, sc, o);
        if (tx == 0)
            g_scores[(isK ? NB * L1 : 0) + g] = sc + bsc;
    }
}

// ---------------------------------------------------------------------------
// Softmax (masked) + score broadcast (branch1), and know softmax -> sk.
// Blocks 0..63: branch1 batch b. Blocks 64..127: know batch b-64.
// ---------------------------------------------------------------------------
__global__ __launch_bounds__(128)
void softmax_kernel(const void* __restrict__ mask1, const void* __restrict__ maskk,
                    float* __restrict__ out) {
    const int mode = g_mask_mode;
    const int t = threadIdx.x;
    if (blockIdx.x < NB) {
        const int b = blockIdx.x;
        __shared__ float red[4];
        __shared__ float sh[L1];
        float scv = g_scores[b * L1 + t];
        bool msk = read_mask(mask1, b * L1 + t, mode);
        float val = msk ? -3.0e38f : scv;
        float mx = val;
        #pragma unroll
        for (int o = 16; o; o >>= 1) mx = fmaxf(mx, __shfl_xor_sync(0xffffffffu, mx, o));
        if ((t & 31) == 0) red[t >> 5] = mx;
        __syncthreads();
        mx = fmaxf(fmaxf(red[0], red[1]), fmaxf(red[2], red[3]));
        __syncthreads();
        float ex = msk ? 0.0f : expf(scv - mx);
        float sm = ex;
        #pragma unroll
        for (int o = 16; o; o >>= 1) sm += __shfl_xor_sync(0xffffffffu, sm, o);
        if ((t & 31) == 0) red[t >> 5] = sm;
        __syncthreads();
        sm = red[0] + red[1] + red[2] + red[3];
        sh[t] = ex / sm;
        __syncthreads();
        // broadcast to (L1, OUTD) as float4 (OUTD % 4 == 0)
        float4* o4 = (float4*)(out + SCORE_OFF + (long)b * L1 * OUTD);
        const int Q = OUTD / 4; // 75
        for (int w = t; w < L1 * Q; w += 128) {
            int row = w / Q, q = w - row * Q;
            float p = sh[row];
            o4[row * Q + q] = make_float4(p, p, p, p);
        }
    } else {
        const int b = blockIdx.x - NB;
        if (t < 32) {
            bool msk = true;
            float scv = 0.0f;
            if (t < KN) {
                msk = read_mask(maskk, b * KN + t, mode);
                scv = g_scores[NB * L1 + b * KN + t];
            }
            float val = (t < KN && !msk) ? scv : -3.0e38f;
            float mx = val;
            #pragma unroll
            for (int o = 16; o; o >>= 1) mx = fmaxf(mx, __shfl_xor_sync(0xffffffffu, mx, o));
            float ex = (t < KN && !msk) ? expf(scv - mx) : 0.0f;
            float sm = ex;
            #pragma unroll
            for (int o = 16; o; o >>= 1) sm += __shfl_xor_sync(0xffffffffu, sm, o);
            if (t < KN) out[SK_OFF + b * KN + t] = ex / sm;
        }
    }
}

extern "C" void kernel_launch(void* const* d_in, const int* in_sizes, int n_in,
                              void* d_out, int out_size) {
    const float* t1    = (const float*)d_in[0];
    const float* know  = (const float*)d_in[1];
    const int*   s1s   = (const int*)d_in[2];
    const int*   s1e   = (const int*)d_in[3];
    const void*  mask1 = d_in[4];
    const int*   sks   = (const int*)d_in[5];
    const int*   ske   = (const int*)d_in[6];
    const void*  maskk = d_in[7];
    const float* W     = (const float*)d_in[8];
    const float* bl    = (const float*)d_in[9];
    const float* gm    = (const float*)d_in[10];
    const float* bt    = (const float*)d_in[11];
    const float* ws    = (const float*)d_in[12];
    const float* bs    = (const float*)d_in[13];
    float* out = (float*)d_out;

    detect_mask_kernel<<<1, 256>>>((const unsigned char*)maskk,
                                   (const unsigned char*)mask1);
    transpose_w_kernel<<<dim3(DDIM / 32, NPAD / 32), dim3(32, 8)>>>(W);
    gemm_ln_kernel<<<NBLK, 256>>>(t1, know, s1s, s1e, sks, ske,
                                  bl, gm, bt, ws, bs, out);
    softmax_kernel<<<2 * NB, 128>>>(mask1, maskk, out);
}

// round 5
// speedup vs baseline: 2.6942x; 2.6942x over previous
#include <cuda_runtime.h>
#include <cuda_bf16.h>
#include <stdint.h>
#include <math.h>

#define NB   64
#define LSEQ 510
#define DDIM 768
#define L1   128
#define KN   20
#define OUTD 300
#define EPSV 1e-5f

#define NSPAN1 (NB * L1)          // 8192
#define NSPANK (NB * KN)          // 1280
#define NSPANS (NSPAN1 + NSPANK)  // 9472
#define TROWS  64
#define NTILES (NSPANS / TROWS)   // 148 == #SMs
#define NBLK1T (NSPAN1 / TROWS)   // 128

#define NCHUNK 12                 // K chunks of 64
#define NPADB  320

#define H1_OFF    0
#define SCORE_OFF (NB * L1 * OUTD)
#define HK_OFF    (2 * NB * L1 * OUTD)
#define SK_OFF    (HK_OFF + NB * KN * OUTD)

#define A_CHUNK_BYTES 8192         // 64 rows x 128B
#define B_CHUNK_BYTES 40960        // 320 rows x 128B

__device__ __align__(16) unsigned char g_Ahi[NTILES * NCHUNK * A_CHUNK_BYTES];
__device__ __align__(16) unsigned char g_Alo[NTILES * NCHUNK * A_CHUNK_BYTES];
__device__ __align__(16) unsigned char g_Bhi[NCHUNK * B_CHUNK_BYTES];
__device__ __align__(16) unsigned char g_Blo[NCHUNK * B_CHUNK_BYTES];
__device__ float g_scores[NSPANS];
__device__ float g_probs[NSPAN1];
__device__ int   g_mask_mode;

// gemm smem layout (dynamic)
#define STAGE_BYTES 98304          // Ahi 8K | Alo 8K | Bhi 40K | Blo 40K
#define OFF_AHI 0
#define OFF_ALO 8192
#define OFF_BHI 16384
#define OFF_BLO 57344
#define SM_TAB  (2 * STAGE_BYTES)          // 196608: 1280 floats
#define SM_RED  (SM_TAB + 5120)            // 201728: 896 floats
#define SMEM_BYTES (SM_RED + 3584)         // 205312

static __device__ __forceinline__ uint32_t smem_u32(const void* p) {
    uint32_t a;
    asm("{ .reg .u64 t; cvta.to.shared.u64 t, %1; cvt.u32.u64 %0, t; }" : "=r"(a) : "l"(p));
    return a;
}
static __device__ __forceinline__ void cp16(uint32_t s, const void* g) {
    asm volatile("cp.async.cg.shared.global [%0], [%1], 16;" :: "r"(s), "l"(g) : "memory");
}
static __device__ __forceinline__ void ldsm4(uint32_t* r, uint32_t addr) {
    asm volatile("ldmatrix.sync.aligned.m8n8.x4.shared.b16 {%0,%1,%2,%3}, [%4];"
                 : "=r"(r[0]), "=r"(r[1]), "=r"(r[2]), "=r"(r[3]) : "r"(addr));
}
static __device__ __forceinline__ void ldsm2(uint32_t* r, uint32_t addr) {
    asm volatile("ldmatrix.sync.aligned.m8n8.x2.shared.b16 {%0,%1}, [%2];"
                 : "=r"(r[0]), "=r"(r[1]) : "r"(addr));
}
static __device__ __forceinline__ void mma16816(float* c, const uint32_t* a,
                                                const uint32_t* b) {
    asm volatile(
        "mma.sync.aligned.m16n8k16.row.col.f32.bf16.bf16.f32 "
        "{%0,%1,%2,%3}, {%4,%5,%6,%7}, {%8,%9}, {%0,%1,%2,%3};"
        : "+f"(c[0]), "+f"(c[1]), "+f"(c[2]), "+f"(c[3])
        : "r"(a[0]), "r"(a[1]), "r"(a[2]), "r"(a[3]), "r"(b[0]), "r"(b[1]));
}
// smem address with per-row XOR swizzle of 16B units (conflict-free ldmatrix)
static __device__ __forceinline__ uint32_t swz_addr(uint32_t base, int row, int u) {
    return base + row * 128 + ((u ^ (row & 7)) << 4);
}

// ---------------------------------------------------------------------------
// prep: blocks 0..9471 span pool+bf16 split; 9472..9791 W convert; 9792 mask
// ---------------------------------------------------------------------------
__global__ __launch_bounds__(96)
void prep_kernel(const float* __restrict__ t1, const float* __restrict__ know,
                 const int* __restrict__ s1s, const int* __restrict__ s1e,
                 const int* __restrict__ sks, const int* __restrict__ ske,
                 const float* __restrict__ W,
                 const unsigned char* __restrict__ mask1,
                 const unsigned char* __restrict__ maskk) {
    const int bid = blockIdx.x;
    const int t = threadIdx.x;
    if (bid < NSPANS) {
        int rid = bid;
        const float* src; int b, s, e;
        if (rid < NSPAN1) { src = t1; b = rid >> 7; s = s1s[rid]; e = s1e[rid]; }
        else { int j = rid - NSPAN1; src = know; b = j / KN; s = sks[j]; e = ske[j]; }
        int len = e - s; if (len < 1) len = 1;
        float inv = 1.0f / (float)len;
        int chunk = t >> 3, grp = t & 7;            // 12 chunks x 8 x 16B
        int c0 = chunk * 64 + grp * 8;
        const float* base = src + ((size_t)(b * LSEQ + s)) * DDIM + c0;
        float v[8];
        #pragma unroll
        for (int j = 0; j < 8; j++) v[j] = 0.0f;
        for (int r = 0; r < len; r++) {
            const float4* p4 = (const float4*)(base + (size_t)r * DDIM);
            float4 a = p4[0], bb = p4[1];
            v[0] += a.x; v[1] += a.y; v[2] += a.z; v[3] += a.w;
            v[4] += bb.x; v[5] += bb.y; v[6] += bb.z; v[7] += bb.w;
        }
        union { unsigned short u[8]; uint4 q; } ph, pl;
        #pragma unroll
        for (int j = 0; j < 8; j++) {
            float x = v[j] * inv;
            __nv_bfloat16 h = __float2bfloat16(x);
            __nv_bfloat16 l = __float2bfloat16(x - __bfloat162float(h));
            ph.u[j] = *(unsigned short*)&h;
            pl.u[j] = *(unsigned short*)&l;
        }
        size_t off = (size_t)((rid >> 6) * NCHUNK + chunk) * A_CHUNK_BYTES
                   + (rid & 63) * 128 + grp * 16;
        *(uint4*)(g_Ahi + off) = ph.q;
        *(uint4*)(g_Alo + off) = pl.q;
    } else if (bid < NSPANS + 320) {
        int idx = (bid - NSPANS) * 96 + t;          // 30720 = 12 * 2560
        int chunk = idx / 2560;
        int rem = idx - chunk * 2560;
        int row = rem >> 3, grp = rem & 7;
        int c0 = chunk * 64 + grp * 8;
        union { unsigned short u[8]; uint4 q; } ph, pl;
        #pragma unroll
        for (int j = 0; j < 8; j++) {
            float x = (row < OUTD) ? W[(size_t)row * DDIM + c0 + j] : 0.0f;
            __nv_bfloat16 h = __float2bfloat16(x);
            __nv_bfloat16 l = __float2bfloat16(x - __bfloat162float(h));
            ph.u[j] = *(unsigned short*)&h;
            pl.u[j] = *(unsigned short*)&l;
        }
        size_t off = (size_t)chunk * B_CHUNK_BYTES + row * 128 + grp * 16;
        *(uint4*)(g_Bhi + off) = ph.q;
        *(uint4*)(g_Blo + off) = pl.q;
    } else {
        __shared__ int f_weird, f_odd;
        if (t == 0) { f_weird = 0; f_odd = 0; }
        __syncthreads();
        int lw = 0, lo = 0;
        for (int i = t; i < NB * KN; i += 96) {
            unsigned char vv = maskk[i];
            if (vv > 1) lw = 1;
            if (vv && (i & 3)) lo = 1;
        }
        for (int i = t; i < NB * L1; i += 96) {
            unsigned char vv = mask1[i];
            if (vv > 1) lw = 1;
            if (vv && (i & 3)) lo = 1;
        }
        if (lw) atomicOr(&f_weird, 1);
        if (lo) atomicOr(&f_odd, 1);
        __syncthreads();
        if (t == 0) g_mask_mode = f_weird ? 2 : (f_odd ? 0 : 1);
    }
}

// ---------------------------------------------------------------------------
// GEMM: warp mma.sync bf16 split (hi*hi + lo*hi + hi*lo into shared fp32 acc),
// double-buffered cp.async, fused bias+LN+score epilogue.
// 148 CTAs x 256 threads. CTA tile: M=64, N=320, K=768.
// ---------------------------------------------------------------------------
__global__ __launch_bounds__(256, 1)
void gemm_kernel(const float* __restrict__ b_lin, const float* __restrict__ gamma,
                 const float* __restrict__ beta, const float* __restrict__ w_score,
                 const float* __restrict__ b_score, float* __restrict__ out) {
    extern __shared__ char smem[];
    const uint32_t sbase = smem_u32(smem);
    const int t = threadIdx.x;
    const int blk = blockIdx.x;
    const int w = t >> 5, lane = t & 31;
    const int wm = w >> 2, wn = w & 3;             // 2 x 4 warp grid
    const int rm0 = wm * 32, nb0 = wn * 80;

    float* tb = (float*)(smem + SM_TAB);           // [0]=bias [320]=g [640]=b [960]=ws
    for (int i = t; i < NPADB; i += 256) {
        tb[i]             = (i < OUTD) ? b_lin[i]   : 0.0f;
        tb[NPADB + i]     = (i < OUTD) ? gamma[i]   : 0.0f;
        tb[2 * NPADB + i] = (i < OUTD) ? beta[i]    : 0.0f;
        tb[3 * NPADB + i] = (i < OUTD) ? w_score[i] : 0.0f;
    }
    __syncthreads();

    float acc[2][10][4];
    #pragma unroll
    for (int mf = 0; mf < 2; mf++)
        #pragma unroll
        for (int nf = 0; nf < 10; nf++)
            #pragma unroll
            for (int q = 0; q < 4; q++) acc[mf][nf][q] = 0.0f;

    const unsigned char* atile_hi = g_Ahi + (size_t)blk * NCHUNK * A_CHUNK_BYTES;
    const unsigned char* atile_lo = g_Alo + (size_t)blk * NCHUNK * A_CHUNK_BYTES;

    // issue chunk 0
    {
        const uint32_t sb = sbase;
        #pragma unroll
        for (int j = 0; j < 2; j++) {
            int idx = t + 256 * j;
            int row = idx >> 3, u = idx & 7;
            uint32_t d = row * 128 + ((u ^ (row & 7)) << 4);
            cp16(sb + OFF_AHI + d, atile_hi + idx * 16);
            cp16(sb + OFF_ALO + d, atile_lo + idx * 16);
        }
        #pragma unroll
        for (int j = 0; j < 10; j++) {
            int idx = t + 256 * j;
            int row = idx >> 3, u = idx & 7;
            uint32_t d = row * 128 + ((u ^ (row & 7)) << 4);
            cp16(sb + OFF_BHI + d, g_Bhi + idx * 16);
            cp16(sb + OFF_BLO + d, g_Blo + idx * 16);
        }
        asm volatile("cp.async.commit_group;" ::: "memory");
    }

    #pragma unroll 1
    for (int c = 0; c < NCHUNK; ++c) {
        if (c + 1 < NCHUNK) {
            const uint32_t sb = sbase + ((c + 1) & 1) * STAGE_BYTES;
            const unsigned char* ah = atile_hi + (size_t)(c + 1) * A_CHUNK_BYTES;
            const unsigned char* al = atile_lo + (size_t)(c + 1) * A_CHUNK_BYTES;
            const unsigned char* bh = g_Bhi + (size_t)(c + 1) * B_CHUNK_BYTES;
            const unsigned char* bl = g_Blo + (size_t)(c + 1) * B_CHUNK_BYTES;
            #pragma unroll
            for (int j = 0; j < 2; j++) {
                int idx = t + 256 * j;
                int row = idx >> 3, u = idx & 7;
                uint32_t d = row * 128 + ((u ^ (row & 7)) << 4);
                cp16(sb + OFF_AHI + d, ah + idx * 16);
                cp16(sb + OFF_ALO + d, al + idx * 16);
            }
            #pragma unroll
            for (int j = 0; j < 10; j++) {
                int idx = t + 256 * j;
                int row = idx >> 3, u = idx & 7;
                uint32_t d = row * 128 + ((u ^ (row & 7)) << 4);
                cp16(sb + OFF_BHI + d, bh + idx * 16);
                cp16(sb + OFF_BLO + d, bl + idx * 16);
            }
            asm volatile("cp.async.commit_group;" ::: "memory");
            asm volatile("cp.async.wait_group 1;" ::: "memory");
        } else {
            asm volatile("cp.async.wait_group 0;" ::: "memory");
        }
        __syncthreads();

        const uint32_t sb = sbase + (c & 1) * STAGE_BYTES;
        const int sub = lane >> 3, rin = lane & 7;
        #pragma unroll
        for (int ks = 0; ks < 4; ks++) {
            uint32_t ah[2][4], al[2][4];
            #pragma unroll
            for (int mf = 0; mf < 2; mf++) {
                int row = rm0 + mf * 16 + rin + ((sub & 1) << 3);
                int u = ks * 2 + (sub >> 1);
                ldsm4(ah[mf], swz_addr(sb + OFF_AHI, row, u));
                ldsm4(al[mf], swz_addr(sb + OFF_ALO, row, u));
            }
            #pragma unroll
            for (int nf = 0; nf < 10; nf++) {
                int brow = nb0 + nf * 8 + rin;
                int bu = ks * 2 + (sub & 1);
                uint32_t bh[2], bl[2];
                ldsm2(bh, swz_addr(sb + OFF_BHI, brow, bu));
                mma16816(acc[0][nf], ah[0], bh);
                mma16816(acc[1][nf], ah[1], bh);
                mma16816(acc[0][nf], al[0], bh);
                mma16816(acc[1][nf], al[1], bh);
                ldsm2(bl, swz_addr(sb + OFF_BLO, brow, bu));
                mma16816(acc[0][nf], ah[0], bl);
                mma16816(acc[1][nf], ah[1], bl);
            }
        }
        __syncthreads();
    }

    // ---- epilogue ----
    float* red_sum  = (float*)(smem + SM_RED);       // [4][64]
    float* red_sq   = red_sum + 256;                 // [4][64]
    float* red_sc   = red_sum + 512;                 // [4][64]
    float* red_mean = red_sum + 768;                 // [64]
    float* red_rstd = red_sum + 832;                 // [64]

    float sum[4] = {0, 0, 0, 0}, sq[4] = {0, 0, 0, 0};
    #pragma unroll
    for (int mf = 0; mf < 2; mf++)
        #pragma unroll
        for (int nf = 0; nf < 10; nf++) {
            int c0 = nb0 + nf * 8 + 2 * (lane & 3);
            float v0 = acc[mf][nf][0] + tb[c0];
            float v1 = acc[mf][nf][1] + tb[c0 + 1];
            float v2 = acc[mf][nf][2] + tb[c0];
            float v3 = acc[mf][nf][3] + tb[c0 + 1];
            sum[mf * 2]     += v0 + v1;  sq[mf * 2]     += v0 * v0 + v1 * v1;
            sum[mf * 2 + 1] += v2 + v3;  sq[mf * 2 + 1] += v2 * v2 + v3 * v3;
        }
    #pragma unroll
    for (int ri = 0; ri < 4; ri++) {
        #pragma unroll
        for (int o = 1; o <= 2; o <<= 1) {
            sum[ri] += __shfl_xor_sync(0xffffffffu, sum[ri], o);
            sq[ri]  += __shfl_xor_sync(0xffffffffu, sq[ri], o);
        }
    }
    if ((lane & 3) == 0) {
        #pragma unroll
        for (int ri = 0; ri < 4; ri++) {
            int row = rm0 + (ri >> 1) * 16 + (ri & 1) * 8 + (lane >> 2);
            red_sum[wn * 64 + row] = sum[ri];
            red_sq[wn * 64 + row]  = sq[ri];
        }
    }
    __syncthreads();
    if (t < TROWS) {
        float s = red_sum[t] + red_sum[64 + t] + red_sum[128 + t] + red_sum[192 + t];
        float q = red_sq[t] + red_sq[64 + t] + red_sq[128 + t] + red_sq[192 + t];
        float mean = s * (1.0f / OUTD);
        float var = q * (1.0f / OUTD) - mean * mean;
        red_mean[t] = mean;
        red_rstd[t] = rsqrtf(fmaxf(var, 0.0f) + EPSV);
    }
    __syncthreads();

    const float* sg  = tb + NPADB;
    const float* sbe = tb + 2 * NPADB;
    const float* sw  = tb + 3 * NPADB;
    float sc[4] = {0, 0, 0, 0};
    #pragma unroll
    for (int mf = 0; mf < 2; mf++) {
        int row01 = rm0 + mf * 16 + (lane >> 2);
        int row23 = row01 + 8;
        float m0 = red_mean[row01], r0 = red_rstd[row01];
        float m1 = red_mean[row23], r1 = red_rstd[row23];
        int g01 = blk * TROWS + row01;
        int g23 = blk * TROWS + row23;
        float* o01 = (blk < NBLK1T) ? out + (size_t)g01 * OUTD
                                    : out + HK_OFF + (size_t)(g01 - NSPAN1) * OUTD;
        float* o23 = (blk < NBLK1T) ? out + (size_t)g23 * OUTD
                                    : out + HK_OFF + (size_t)(g23 - NSPAN1) * OUTD;
        #pragma unroll
        for (int nf = 0; nf < 10; nf++) {
            int c0 = nb0 + nf * 8 + 2 * (lane & 3);
            float v0 = acc[mf][nf][0] + tb[c0];
            float v1 = acc[mf][nf][1] + tb[c0 + 1];
            float v2 = acc[mf][nf][2] + tb[c0];
            float v3 = acc[mf][nf][3] + tb[c0 + 1];
            float h0 = (v0 - m0) * r0 * sg[c0]     + sbe[c0];
            float h1 = (v1 - m0) * r0 * sg[c0 + 1] + sbe[c0 + 1];
            float h2 = (v2 - m1) * r1 * sg[c0]     + sbe[c0];
            float h3 = (v3 - m1) * r1 * sg[c0 + 1] + sbe[c0 + 1];
            sc[mf * 2]     += h0 * sw[c0] + h1 * sw[c0 + 1];
            sc[mf * 2 + 1] += h2 * sw[c0] + h3 * sw[c0 + 1];
            if (c0 < OUTD) {
                *(float2*)(o01 + c0) = make_float2(h0, h1);
                *(float2*)(o23 + c0) = make_float2(h2, h3);
            }
        }
    }
    #pragma unroll
    for (int ri = 0; ri < 4; ri++)
        #pragma unroll
        for (int o = 1; o <= 2; o <<= 1)
            sc[ri] += __shfl_xor_sync(0xffffffffu, sc[ri], o);
    if ((lane & 3) == 0) {
        #pragma unroll
        for (int ri = 0; ri < 4; ri++) {
            int row = rm0 + (ri >> 1) * 16 + (ri & 1) * 8 + (lane >> 2);
            red_sc[wn * 64 + row] = sc[ri];
        }
    }
    __syncthreads();
    if (t < TROWS) {
        g_scores[blk * TROWS + t] =
            red_sc[t] + red_sc[64 + t] + red_sc[128 + t] + red_sc[192 + t] + b_score[0];
    }
}

// ---------------------------------------------------------------------------
static __device__ __forceinline__ bool read_mask(const void* m, int i, int mode) {
    if (mode == 0) return ((const unsigned char*)m)[i] != 0;
    if (mode == 1) return ((const int*)m)[i] != 0;
    return ((const float*)m)[i] != 0.0f;
}

__global__ __launch_bounds__(128)
void softmax_kernel(const void* __restrict__ mask1, const void* __restrict__ maskk,
                    float* __restrict__ out) {
    const int mode = g_mask_mode;
    const int t = threadIdx.x;
    if (blockIdx.x < NB) {
        const int b = blockIdx.x;
        __shared__ float red[4];
        float scv = g_scores[b * L1 + t];
        bool msk = read_mask(mask1, b * L1 + t, mode);
        float val = msk ? -3.0e38f : scv;
        float mx = val;
        #pragma unroll
        for (int o = 16; o; o >>= 1) mx = fmaxf(mx, __shfl_xor_sync(0xffffffffu, mx, o));
        if ((t & 31) == 0) red[t >> 5] = mx;
        __syncthreads();
        mx = fmaxf(fmaxf(red[0], red[1]), fmaxf(red[2], red[3]));
        __syncthreads();
        float ex = msk ? 0.0f : expf(scv - mx);
        float sm = ex;
        #pragma unroll
        for (int o = 16; o; o >>= 1) sm += __shfl_xor_sync(0xffffffffu, sm, o);
        if ((t & 31) == 0) red[t >> 5] = sm;
        __syncthreads();
        sm = red[0] + red[1] + red[2] + red[3];
        g_probs[b * L1 + t] = ex / sm;
    } else {
        const int b = blockIdx.x - NB;
        if (t < 32) {
            bool msk = true;
            float scv = 0.0f;
            if (t < KN) {
                msk = read_mask(maskk, b * KN + t, mode);
                scv = g_scores[NSPAN1 + b * KN + t];
            }
            float val = (t < KN && !msk) ? scv : -3.0e38f;
            float mx = val;
            #pragma unroll
            for (int o = 16; o; o >>= 1) mx = fmaxf(mx, __shfl_xor_sync(0xffffffffu, mx, o));
            float ex = (t < KN && !msk) ? expf(scv - mx) : 0.0f;
            float sm = ex;
            #pragma unroll
            for (int o = 16; o; o >>= 1) sm += __shfl_xor_sync(0xffffffffu, sm, o);
            if (t < KN) out[SK_OFF + b * KN + t] = ex / sm;
        }
    }
}

#define BCAST_F4 (NSPAN1 * (OUTD / 4))   // 614400
__global__ __launch_bounds__(256)
void broadcast_kernel(float* __restrict__ out) {
    float4* o4 = (float4*)(out + SCORE_OFF);
    const int stride = gridDim.x * blockDim.x;
    for (int ww = blockIdx.x * blockDim.x + threadIdx.x; ww < BCAST_F4; ww += stride) {
        const float p = g_probs[ww / (OUTD / 4)];
        o4[ww] = make_float4(p, p, p, p);
    }
}

extern "C" void kernel_launch(void* const* d_in, const int* in_sizes, int n_in,
                              void* d_out, int out_size) {
    const float* t1    = (const float*)d_in[0];
    const float* know  = (const float*)d_in[1];
    const int*   s1s   = (const int*)d_in[2];
    const int*   s1e   = (const int*)d_in[3];
    const void*  mask1 = d_in[4];
    const int*   sks   = (const int*)d_in[5];
    const int*   ske   = (const int*)d_in[6];
    const void*  maskk = d_in[7];
    const float* W     = (const float*)d_in[8];
    const float* bl    = (const float*)d_in[9];
    const float* gm    = (const float*)d_in[10];
    const float* bt    = (const float*)d_in[11];
    const float* ws    = (const float*)d_in[12];
    const float* bs    = (const float*)d_in[13];
    float* out = (float*)d_out;

    cudaFuncSetAttribute(gemm_kernel, cudaFuncAttributeMaxDynamicSharedMemorySize,
                         SMEM_BYTES);
    prep_kernel<<<NSPANS + 321, 96>>>(t1, know, s1s, s1e, sks, ske, W,
                                      (const unsigned char*)mask1,
                                      (const unsigned char*)maskk);
    gemm_kernel<<<NTILES, 256, SMEM_BYTES>>>(bl, gm, bt, ws, bs, out);
    softmax_kernel<<<2 * NB, 128>>>(mask1, maskk, out);
    broadcast_kernel<<<600, 256>>>(out);
}

// round 7
// speedup vs baseline: 2.9364x; 1.0899x over previous
#include <cuda_runtime.h>
#include <cuda_bf16.h>
#include <stdint.h>
#include <math.h>

#define NB   64
#define LSEQ 510
#define DDIM 768
#define L1   128
#define KN   20
#define OUTD 300
#define EPSV 1e-5f

#define NSPAN1 (NB * L1)          // 8192
#define NSPANK (NB * KN)          // 1280
#define NSPANS (NSPAN1 + NSPANK)  // 9472
#define TROWS  64
#define NTILES (NSPANS / TROWS)   // 148 == #SMs
#define NBLK1T (NSPAN1 / TROWS)   // 128

#define NCHUNK 12                 // K chunks of 64
#define NPADB  320

#define H1_OFF    0
#define SCORE_OFF (NB * L1 * OUTD)
#define HK_OFF    (2 * NB * L1 * OUTD)
#define SK_OFF    (HK_OFF + NB * KN * OUTD)

#define A_CHUNK_BYTES 8192         // 64 rows x 128B
#define B_CHUNK_BYTES 40960        // 320 rows x 128B

__device__ __align__(16) unsigned char g_Ahi[NTILES * NCHUNK * A_CHUNK_BYTES];
__device__ __align__(16) unsigned char g_Alo[NTILES * NCHUNK * A_CHUNK_BYTES];
__device__ __align__(16) unsigned char g_Bhi[NCHUNK * B_CHUNK_BYTES];
__device__ __align__(16) unsigned char g_Blo[NCHUNK * B_CHUNK_BYTES];
__device__ float g_scores[NSPANS];
__device__ int   g_mask_mode;

// gemm smem layout (dynamic)
#define STAGE_BYTES 98304          // Ahi 8K | Alo 8K | Bhi 40K | Blo 40K
#define OFF_AHI 0
#define OFF_ALO 8192
#define OFF_BHI 16384
#define OFF_BLO 57344
#define SM_TAB  (2 * STAGE_BYTES)
#define SM_RED  (SM_TAB + 5120)
#define SMEM_BYTES (SM_RED + 3584)

static __device__ __forceinline__ uint32_t smem_u32(const void* p) {
    uint32_t a;
    asm("{ .reg .u64 t; cvta.to.shared.u64 t, %1; cvt.u32.u64 %0, t; }" : "=r"(a) : "l"(p));
    return a;
}
static __device__ __forceinline__ void cp16(uint32_t s, const void* g) {
    asm volatile("cp.async.cg.shared.global [%0], [%1], 16;" :: "r"(s), "l"(g) : "memory");
}
static __device__ __forceinline__ void ldsm4(uint32_t* r, uint32_t addr) {
    asm volatile("ldmatrix.sync.aligned.m8n8.x4.shared.b16 {%0,%1,%2,%3}, [%4];"
                 : "=r"(r[0]), "=r"(r[1]), "=r"(r[2]), "=r"(r[3]) : "r"(addr));
}
static __device__ __forceinline__ void ldsm2(uint32_t* r, uint32_t addr) {
    asm volatile("ldmatrix.sync.aligned.m8n8.x2.shared.b16 {%0,%1}, [%2];"
                 : "=r"(r[0]), "=r"(r[1]) : "r"(addr));
}
static __device__ __forceinline__ void mma16816(float* c, const uint32_t* a,
                                                const uint32_t* b) {
    asm volatile(
        "mma.sync.aligned.m16n8k16.row.col.f32.bf16.bf16.f32 "
        "{%0,%1,%2,%3}, {%4,%5,%6,%7}, {%8,%9}, {%0,%1,%2,%3};"
        : "+f"(c[0]), "+f"(c[1]), "+f"(c[2]), "+f"(c[3])
        : "r"(a[0]), "r"(a[1]), "r"(a[2]), "r"(a[3]), "r"(b[0]), "r"(b[1]));
}
static __device__ __forceinline__ uint32_t swz_addr(uint32_t base, int row, int u) {
    return base + row * 128 + ((u ^ (row & 7)) << 4);
}
static __device__ __forceinline__ void split_store(const float* v, float inv,
                                                   unsigned char* dhi,
                                                   unsigned char* dlo) {
    union { unsigned short u[8]; uint4 q; } ph, pl;
    #pragma unroll
    for (int j = 0; j < 8; j++) {
        float x = v[j] * inv;
        __nv_bfloat16 h = __float2bfloat16(x);
        __nv_bfloat16 l = __float2bfloat16(x - __bfloat162float(h));
        ph.u[j] = *(unsigned short*)&h;
        pl.u[j] = *(unsigned short*)&l;
    }
    *(uint4*)dhi = ph.q;
    *(uint4*)dlo = pl.q;
}

// ---------------------------------------------------------------------------
// prep: blocks [0,1184): warp-per-span pooling+split (8 spans/block);
//       blocks [1184,1304): W convert; block 1304: mask detect.
// ---------------------------------------------------------------------------
#define PREP_SPAN_BLKS (NSPANS / 8)   // 1184
#define PREP_W_BLKS    120            // 120*256 = 30720 = 320*96 units
#define PREP_BLKS      (PREP_SPAN_BLKS + PREP_W_BLKS + 1)

__global__ __launch_bounds__(256)
void prep_kernel(const float* __restrict__ t1, const float* __restrict__ know,
                 const int* __restrict__ s1s, const int* __restrict__ s1e,
                 const int* __restrict__ sks, const int* __restrict__ ske,
                 const float* __restrict__ W,
                 const unsigned char* __restrict__ mask1,
                 const unsigned char* __restrict__ maskk) {
    const int bid = blockIdx.x;
    const int t = threadIdx.x;
    if (bid < PREP_SPAN_BLKS) {
        const int w = t >> 5, lane = t & 31;
        const int rid = bid * 8 + w;
        const float* src; int b, s, e;
        if (rid < NSPAN1) { src = t1; b = rid >> 7; s = s1s[rid]; e = s1e[rid]; }
        else { int j = rid - NSPAN1; src = know; b = j / KN; s = sks[j]; e = ske[j]; }
        int len = e - s; if (len < 1) len = 1;
        const float inv = 1.0f / (float)len;
        const float* base = src + (size_t)(b * LSEQ + s) * DDIM;
        const int tile = rid >> 6, r = rid & 63;
        #pragma unroll
        for (int g = 0; g < 3; g++) {
            const int idx8 = g * 32 + lane;     // 0..95
            const int c0 = idx8 * 8;
            float v[8];
            #pragma unroll
            for (int j = 0; j < 8; j++) v[j] = 0.0f;
            for (int rr = 0; rr < len; rr++) {
                const float4* p4 = (const float4*)(base + (size_t)rr * DDIM + c0);
                float4 a = p4[0], bb = p4[1];
                v[0] += a.x; v[1] += a.y; v[2] += a.z; v[3] += a.w;
                v[4] += bb.x; v[5] += bb.y; v[6] += bb.z; v[7] += bb.w;
            }
            const int chunk = idx8 >> 3, grp = idx8 & 7;
            size_t off = (size_t)(tile * NCHUNK + chunk) * A_CHUNK_BYTES
                       + r * 128 + grp * 16;
            split_store(v, inv, g_Ahi + off, g_Alo + off);
        }
    } else if (bid < PREP_SPAN_BLKS + PREP_W_BLKS) {
        const int u = (bid - PREP_SPAN_BLKS) * 256 + t;   // [0, 30720)
        const int row = u / 96;
        const int idx8 = u - row * 96;
        const int c0 = idx8 * 8;
        float v[8];
        if (row < OUTD) {
            const float4* p4 = (const float4*)(W + (size_t)row * DDIM + c0);
            float4 a = p4[0], bb = p4[1];
            v[0] = a.x; v[1] = a.y; v[2] = a.z; v[3] = a.w;
            v[4] = bb.x; v[5] = bb.y; v[6] = bb.z; v[7] = bb.w;
        } else {
            #pragma unroll
            for (int j = 0; j < 8; j++) v[j] = 0.0f;
        }
        const int chunk = idx8 >> 3, grp = idx8 & 7;
        size_t off = (size_t)chunk * B_CHUNK_BYTES + row * 128 + grp * 16;
        split_store(v, 1.0f, g_Bhi + off, g_Blo + off);
    } else {
        __shared__ int f_weird, f_odd;
        if (t == 0) { f_weird = 0; f_odd = 0; }
        __syncthreads();
        int lw = 0, lo = 0;
        for (int i = t; i < NB * KN; i += 256) {
            unsigned char vv = maskk[i];
            if (vv > 1) lw = 1;
            if (vv && (i & 3)) lo = 1;
        }
        for (int i = t; i < NB * L1; i += 256) {
            unsigned char vv = mask1[i];
            if (vv > 1) lw = 1;
            if (vv && (i & 3)) lo = 1;
        }
        if (lw) atomicOr(&f_weird, 1);
        if (lo) atomicOr(&f_odd, 1);
        __syncthreads();
        if (t == 0) g_mask_mode = f_weird ? 2 : (f_odd ? 0 : 1);
    }
}

// ---------------------------------------------------------------------------
// GEMM: unchanged from R5 (validated). 148 CTAs x 256. M=64,N=320,K=768.
// ---------------------------------------------------------------------------
__global__ __launch_bounds__(256, 1)
void gemm_kernel(const float* __restrict__ b_lin, const float* __restrict__ gamma,
                 const float* __restrict__ beta, const float* __restrict__ w_score,
                 const float* __restrict__ b_score, float* __restrict__ out) {
    extern __shared__ char smem[];
    const uint32_t sbase = smem_u32(smem);
    const int t = threadIdx.x;
    const int blk = blockIdx.x;
    const int w = t >> 5, lane = t & 31;
    const int wm = w >> 2, wn = w & 3;
    const int rm0 = wm * 32, nb0 = wn * 80;

    float* tb = (float*)(smem + SM_TAB);
    for (int i = t; i < NPADB; i += 256) {
        tb[i]             = (i < OUTD) ? b_lin[i]   : 0.0f;
        tb[NPADB + i]     = (i < OUTD) ? gamma[i]   : 0.0f;
        tb[2 * NPADB + i] = (i < OUTD) ? beta[i]    : 0.0f;
        tb[3 * NPADB + i] = (i < OUTD) ? w_score[i] : 0.0f;
    }
    __syncthreads();

    float acc[2][10][4];
    #pragma unroll
    for (int mf = 0; mf < 2; mf++)
        #pragma unroll
        for (int nf = 0; nf < 10; nf++)
            #pragma unroll
            for (int q = 0; q < 4; q++) acc[mf][nf][q] = 0.0f;

    const unsigned char* atile_hi = g_Ahi + (size_t)blk * NCHUNK * A_CHUNK_BYTES;
    const unsigned char* atile_lo = g_Alo + (size_t)blk * NCHUNK * A_CHUNK_BYTES;

    {
        const uint32_t sb = sbase;
        #pragma unroll
        for (int j = 0; j < 2; j++) {
            int idx = t + 256 * j;
            int row = idx >> 3, u = idx & 7;
            uint32_t d = row * 128 + ((u ^ (row & 7)) << 4);
            cp16(sb + OFF_AHI + d, atile_hi + idx * 16);
            cp16(sb + OFF_ALO + d, atile_lo + idx * 16);
        }
        #pragma unroll
        for (int j = 0; j < 10; j++) {
            int idx = t + 256 * j;
            int row = idx >> 3, u = idx & 7;
            uint32_t d = row * 128 + ((u ^ (row & 7)) << 4);
            cp16(sb + OFF_BHI + d, g_Bhi + idx * 16);
            cp16(sb + OFF_BLO + d, g_Blo + idx * 16);
        }
        asm volatile("cp.async.commit_group;" ::: "memory");
    }

    #pragma unroll 1
    for (int c = 0; c < NCHUNK; ++c) {
        if (c + 1 < NCHUNK) {
            const uint32_t sb = sbase + ((c + 1) & 1) * STAGE_BYTES;
            const unsigned char* ah = atile_hi + (size_t)(c + 1) * A_CHUNK_BYTES;
            const unsigned char* al = atile_lo + (size_t)(c + 1) * A_CHUNK_BYTES;
            const unsigned char* bh = g_Bhi + (size_t)(c + 1) * B_CHUNK_BYTES;
            const unsigned char* bl = g_Blo + (size_t)(c + 1) * B_CHUNK_BYTES;
            #pragma unroll
            for (int j = 0; j < 2; j++) {
                int idx = t + 256 * j;
                int row = idx >> 3, u = idx & 7;
                uint32_t d = row * 128 + ((u ^ (row & 7)) << 4);
                cp16(sb + OFF_AHI + d, ah + idx * 16);
                cp16(sb + OFF_ALO + d, al + idx * 16);
            }
            #pragma unroll
            for (int j = 0; j < 10; j++) {
                int idx = t + 256 * j;
                int row = idx >> 3, u = idx & 7;
                uint32_t d = row * 128 + ((u ^ (row & 7)) << 4);
                cp16(sb + OFF_BHI + d, bh + idx * 16);
                cp16(sb + OFF_BLO + d, bl + idx * 16);
            }
            asm volatile("cp.async.commit_group;" ::: "memory");
            asm volatile("cp.async.wait_group 1;" ::: "memory");
        } else {
            asm volatile("cp.async.wait_group 0;" ::: "memory");
        }
        __syncthreads();

        const uint32_t sb = sbase + (c & 1) * STAGE_BYTES;
        const int sub = lane >> 3, rin = lane & 7;
        #pragma unroll
        for (int ks = 0; ks < 4; ks++) {
            uint32_t ah[2][4], al[2][4];
            #pragma unroll
            for (int mf = 0; mf < 2; mf++) {
                int row = rm0 + mf * 16 + rin + ((sub & 1) << 3);
                int u = ks * 2 + (sub >> 1);
                ldsm4(ah[mf], swz_addr(sb + OFF_AHI, row, u));
                ldsm4(al[mf], swz_addr(sb + OFF_ALO, row, u));
            }
            #pragma unroll
            for (int nf = 0; nf < 10; nf++) {
                int brow = nb0 + nf * 8 + rin;
                int bu = ks * 2 + (sub & 1);
                uint32_t bh[2], bl[2];
                ldsm2(bh, swz_addr(sb + OFF_BHI, brow, bu));
                mma16816(acc[0][nf], ah[0], bh);
                mma16816(acc[1][nf], ah[1], bh);
                mma16816(acc[0][nf], al[0], bh);
                mma16816(acc[1][nf], al[1], bh);
                ldsm2(bl, swz_addr(sb + OFF_BLO, brow, bu));
                mma16816(acc[0][nf], ah[0], bl);
                mma16816(acc[1][nf], ah[1], bl);
            }
        }
        __syncthreads();
    }

    // ---- epilogue ----
    float* red_sum  = (float*)(smem + SM_RED);
    float* red_sq   = red_sum + 256;
    float* red_sc   = red_sum + 512;
    float* red_mean = red_sum + 768;
    float* red_rstd = red_sum + 832;

    float sum[4] = {0, 0, 0, 0}, sq[4] = {0, 0, 0, 0};
    #pragma unroll
    for (int mf = 0; mf < 2; mf++)
        #pragma unroll
        for (int nf = 0; nf < 10; nf++) {
            int c0 = nb0 + nf * 8 + 2 * (lane & 3);
            float v0 = acc[mf][nf][0] + tb[c0];
            float v1 = acc[mf][nf][1] + tb[c0 + 1];
            float v2 = acc[mf][nf][2] + tb[c0];
            float v3 = acc[mf][nf][3] + tb[c0 + 1];
            sum[mf * 2]     += v0 + v1;  sq[mf * 2]     += v0 * v0 + v1 * v1;
            sum[mf * 2 + 1] += v2 + v3;  sq[mf * 2 + 1] += v2 * v2 + v3 * v3;
        }
    #pragma unroll
    for (int ri = 0; ri < 4; ri++) {
        #pragma unroll
        for (int o = 1; o <= 2; o <<= 1) {
            sum[ri] += __shfl_xor_sync(0xffffffffu, sum[ri], o);
            sq[ri]  += __shfl_xor_sync(0xffffffffu, sq[ri], o);
        }
    }
    if ((lane & 3) == 0) {
        #pragma unroll
        for (int ri = 0; ri < 4; ri++) {
            int row = rm0 + (ri >> 1) * 16 + (ri & 1) * 8 + (lane >> 2);
            red_sum[wn * 64 + row] = sum[ri];
            red_sq[wn * 64 + row]  = sq[ri];
        }
    }
    __syncthreads();
    if (t < TROWS) {
        float s = red_sum[t] + red_sum[64 + t] + red_sum[128 + t] + red_sum[192 + t];
        float q = red_sq[t] + red_sq[64 + t] + red_sq[128 + t] + red_sq[192 + t];
        float mean = s * (1.0f / OUTD);
        float var = q * (1.0f / OUTD) - mean * mean;
        red_mean[t] = mean;
        red_rstd[t] = rsqrtf(fmaxf(var, 0.0f) + EPSV);
    }
    __syncthreads();

    const float* sg  = tb + NPADB;
    const float* sbe = tb + 2 * NPADB;
    const float* sw  = tb + 3 * NPADB;
    float sc[4] = {0, 0, 0, 0};
    #pragma unroll
    for (int mf = 0; mf < 2; mf++) {
        int row01 = rm0 + mf * 16 + (lane >> 2);
        int row23 = row01 + 8;
        float m0 = red_mean[row01], r0 = red_rstd[row01];
        float m1 = red_mean[row23], r1 = red_rstd[row23];
        int g01 = blk * TROWS + row01;
        int g23 = blk * TROWS + row23;
        float* o01 = (blk < NBLK1T) ? out + (size_t)g01 * OUTD
                                    : out + HK_OFF + (size_t)(g01 - NSPAN1) * OUTD;
        float* o23 = (blk < NBLK1T) ? out + (size_t)g23 * OUTD
                                    : out + HK_OFF + (size_t)(g23 - NSPAN1) * OUTD;
        #pragma unroll
        for (int nf = 0; nf < 10; nf++) {
            int c0 = nb0 + nf * 8 + 2 * (lane & 3);
            float v0 = acc[mf][nf][0] + tb[c0];
            float v1 = acc[mf][nf][1] + tb[c0 + 1];
            float v2 = acc[mf][nf][2] + tb[c0];
            float v3 = acc[mf][nf][3] + tb[c0 + 1];
            float h0 = (v0 - m0) * r0 * sg[c0]     + sbe[c0];
            float h1 = (v1 - m0) * r0 * sg[c0 + 1] + sbe[c0 + 1];
            float h2 = (v2 - m1) * r1 * sg[c0]     + sbe[c0];
            float h3 = (v3 - m1) * r1 * sg[c0 + 1] + sbe[c0 + 1];
            sc[mf * 2]     += h0 * sw[c0] + h1 * sw[c0 + 1];
            sc[mf * 2 + 1] += h2 * sw[c0] + h3 * sw[c0 + 1];
            if (c0 < OUTD) {
                *(float2*)(o01 + c0) = make_float2(h0, h1);
                *(float2*)(o23 + c0) = make_float2(h2, h3);
            }
        }
    }
    #pragma unroll
    for (int ri = 0; ri < 4; ri++)
        #pragma unroll
        for (int o = 1; o <= 2; o <<= 1)
            sc[ri] += __shfl_xor_sync(0xffffffffu, sc[ri], o);
    if ((lane & 3) == 0) {
        #pragma unroll
        for (int ri = 0; ri < 4; ri++) {
            int row = rm0 + (ri >> 1) * 16 + (ri & 1) * 8 + (lane >> 2);
            red_sc[wn * 64 + row] = sc[ri];
        }
    }
    __syncthreads();
    if (t < TROWS) {
        g_scores[blk * TROWS + t] =
            red_sc[t] + red_sc[64 + t] + red_sc[128 + t] + red_sc[192 + t] + b_score[0];
    }
}

// ---------------------------------------------------------------------------
// fused softmax + broadcast: blocks 0..63 branch1 softmax + (L1 x OUTD) bcast;
// blocks 64..127 know softmax.
// ---------------------------------------------------------------------------
static __device__ __forceinline__ bool read_mask(const void* m, int i, int mode) {
    if (mode == 0) return ((const unsigned char*)m)[i] != 0;
    if (mode == 1) return ((const int*)m)[i] != 0;
    return ((const float*)m)[i] != 0.0f;
}

__global__ __launch_bounds__(256)
void softmax_bcast_kernel(const void* __restrict__ mask1,
                          const void* __restrict__ maskk,
                          float* __restrict__ out) {
    const int mode = g_mask_mode;
    const int t = threadIdx.x;
    if (blockIdx.x < NB) {
        const int b = blockIdx.x;
        __shared__ float red[4];
        __shared__ float sh[L1];
        float scv = 0.0f; bool msk = true;
        if (t < L1) {
            scv = g_scores[b * L1 + t];
            msk = read_mask(mask1, b * L1 + t, mode);
        }
        float val = (t < L1 && !msk) ? scv : -3.0e38f;
        float mx = val;
        #pragma unroll
        for (int o = 16; o; o >>= 1) mx = fmaxf(mx, __shfl_xor_sync(0xffffffffu, mx, o));
        if (t < L1 && (t & 31) == 0) red[t >> 5] = mx;
        __syncthreads();
        mx = fmaxf(fmaxf(red[0], red[1]), fmaxf(red[2], red[3]));
        __syncthreads();
        float ex = (t < L1 && !msk) ? expf(scv - mx) : 0.0f;
        float sm = ex;
        #pragma unroll
        for (int o = 16; o; o >>= 1) sm += __shfl_xor_sync(0xffffffffu, sm, o);
        if (t < L1 && (t & 31) == 0) red[t >> 5] = sm;
        __syncthreads();
        sm = red[0] + red[1] + red[2] + red[3];
        if (t < L1) sh[t] = ex / sm;
        __syncthreads();
        float4* o4 = (float4*)(out + SCORE_OFF + (size_t)b * L1 * OUTD);
        const int Q = OUTD / 4;            // 75
        for (int w2 = t; w2 < L1 * Q; w2 += 256) {
            int row = w2 / Q;
            float p = sh[row];
            o4[w2] = make_float4(p, p, p, p);
        }
    } else {
        const int b = blockIdx.x - NB;
        if (t < 32) {
            bool msk = true;
            float scv = 0.0f;
            if (t < KN) {
                msk = read_mask(maskk, b * KN + t, mode);
                scv = g_scores[NSPAN1 + b * KN + t];
            }
            float val = (t < KN && !msk) ? scv : -3.0e38f;
            float mx = val;
            #pragma unroll
            for (int o = 16; o; o >>= 1) mx = fmaxf(mx, __shfl_xor_sync(0xffffffffu, mx, o));
            float ex = (t < KN && !msk) ? expf(scv - mx) : 0.0f;
            float sm = ex;
            #pragma unroll
            for (int o = 16; o; o >>= 1) sm += __shfl_xor_sync(0xffffffffu, sm, o);
            if (t < KN) out[SK_OFF + b * KN + t] = ex / sm;
        }
    }
}

// no-op tail kernel: aligns ncu's "-s 5 -c 1" capture onto gemm_kernel
__global__ void profile_pad_kernel() {}

extern "C" void kernel_launch(void* const* d_in, const int* in_sizes, int n_in,
                              void* d_out, int out_size) {
    const float* t1    = (const float*)d_in[0];
    const float* know  = (const float*)d_in[1];
    const int*   s1s   = (const int*)d_in[2];
    const int*   s1e   = (const int*)d_in[3];
    const void*  mask1 = d_in[4];
    const int*   sks   = (const int*)d_in[5];
    const int*   ske   = (const int*)d_in[6];
    const void*  maskk = d_in[7];
    const float* W     = (const float*)d_in[8];
    const float* bl    = (const float*)d_in[9];
    const float* gm    = (const float*)d_in[10];
    const float* bt    = (const float*)d_in[11];
    const float* ws    = (const float*)d_in[12];
    const float* bs    = (const float*)d_in[13];
    float* out = (float*)d_out;

    cudaFuncSetAttribute(gemm_kernel, cudaFuncAttributeMaxDynamicSharedMemorySize,
                         SMEM_BYTES);
    prep_kernel<<<PREP_BLKS, 256>>>(t1, know, s1s, s1e, sks, ske, W,
                                    (const unsigned char*)mask1,
                                    (const unsigned char*)maskk);
    gemm_kernel<<<NTILES, 256, SMEM_BYTES>>>(bl, gm, bt, ws, bs, out);
    softmax_bcast_kernel<<<2 * NB, 256>>>(mask1, maskk, out);
    profile_pad_kernel<<<1, 32>>>();
}